// round 17
// baseline (speedup 1.0000x reference)
#include <cuda_runtime.h>
#include <cuda_fp16.h>
#include <math.h>

// Problem constants
constexpr int B_   = 2;
constexpr int S_   = 2048;
constexpr int DIM_ = 4096;
constexpr int NH_  = 32;
constexpr int NKV_ = 8;
constexpr int HD_  = 128;
constexpr int KVW_ = NKV_ * HD_;       // 1024
constexpr int NQKV = DIM_ + 2 * KVW_;  // 6144

// ---------------------------------------------------------------------------
// Scratch (module-scope device arrays; allocation-free at launch time)
// ---------------------------------------------------------------------------
__device__ __half g_xhi[16777216];                       // x fp16
__device__ __half g_wqkv[25165824];                      // [wq;wk;wv] (6144 x 4096)
__device__ __half g_wohi[16777216];
__device__ __half g_qhi[16777216];                       // q fp16 post-rope [b,s,h,d]
__device__ __half g_khi[4194304];                        // k fp16 post-rope [b,s,kv,d]
__device__ __half g_vthi[4194304];                       // V fp16 transposed [b,kv,d,s]
__device__ __half g_ahi[16777216];                       // attn fp16 [b,s,h,d]

// ---------------------------------------------------------------------------
// PTX helpers — sm_80-era only (compute_103 virtual arch: NO tcgen05)
// ---------------------------------------------------------------------------
__device__ __forceinline__ unsigned smem_u32(const void* p) {
    return (unsigned)__cvta_generic_to_shared(p);
}
__device__ __forceinline__ void cpa16(unsigned dst, const void* src) {
    asm volatile("cp.async.cg.shared.global [%0], [%1], 16;" :: "r"(dst), "l"(src) : "memory");
}
__device__ __forceinline__ void cpa_commit() {
    asm volatile("cp.async.commit_group;" ::: "memory");
}
__device__ __forceinline__ void cpa_wait1() {
    asm volatile("cp.async.wait_group 1;" ::: "memory");
}
__device__ __forceinline__ void cpa_wait0() {
    asm volatile("cp.async.wait_group 0;" ::: "memory");
}
__device__ __forceinline__ void ldsm4(unsigned* r, unsigned a) {
    asm volatile("ldmatrix.sync.aligned.m8n8.x4.shared.b16 {%0,%1,%2,%3}, [%4];"
                 : "=r"(r[0]), "=r"(r[1]), "=r"(r[2]), "=r"(r[3]) : "r"(a));
}
__device__ __forceinline__ void mma16816(float* c, const unsigned* a, const unsigned* b) {
    asm volatile("mma.sync.aligned.m16n8k16.row.col.f32.f16.f16.f32 "
                 "{%0,%1,%2,%3}, {%4,%5,%6,%7}, {%8,%9}, {%0,%1,%2,%3};"
                 : "+f"(c[0]), "+f"(c[1]), "+f"(c[2]), "+f"(c[3])
                 : "r"(a[0]), "r"(a[1]), "r"(a[2]), "r"(a[3]), "r"(b[0]), "r"(b[1]));
}

// ===========================================================================
// Projection GEMM: 256x128 block tile, 8 warps (4x2), warp tile 64x64, KC=64.
// Bigger M-tile => each B fragment feeds 4 M-subtiles: smem read traffic
// drops to 0.0625 B/MAC (was 0.094) — the measured binder is the LDS
// crossbar, not HMMA issue.
// SMEM: 144B pitch rows; A 256x64h, B 128x64h; double buffered = 110592 B.
// EPI=0: fp32 C (out-proj).
// EPI=3: fused QKV epilogue: col<4096 RoPE->qhi; col<5120 RoPE->khi;
//        else V fp16 directly transposed into vthi [b,kv,d,s].
// ===========================================================================
constexpr int GPITCH = 144;
constexpr int GSUBTA = 256 * GPITCH;           // 36864 B (A subtile)
constexpr int GSTAGE = GSUBTA + 128 * GPITCH;  // 55296 B
constexpr int GSMEM  = 2 * GSTAGE;             // 110592 B (occ 1)

template <int EPI>
__global__ __launch_bounds__(256, 1)
void gemm64(const __half* __restrict__ A, const __half* __restrict__ Bm,
            float* __restrict__ Cf,
            __half* __restrict__ qp, __half* __restrict__ kp, __half* __restrict__ vp,
            const float* __restrict__ cs, const float* __restrict__ sn,
            int K, int lda, int ldb, int ldc)
{
    const int bm0 = blockIdx.y * 256;
    const int bn0 = blockIdx.x * 128;

    extern __shared__ char smem[];
    const unsigned sb = smem_u32(smem);
    const int tid  = threadIdx.x;
    const int lane = tid & 31;
    const int wid  = tid >> 5;
    const int wm   = wid & 3;     // 4 warp-rows x 64 = 256
    const int wn   = wid >> 2;    // 2 warp-cols x 64 = 128

    const int nk = K >> 6;

    auto stage = [&](int si) {
        const unsigned base = sb + (si & 1) * GSTAGE;
        const int kc = si * 64;
        #pragma unroll
        for (int it = 0; it < 12; it++) {
            if (it < 8) {          // A: 256 rows x 8 segs
                const int idx = tid + it * 256;
                const int row = idx >> 3, seg = idx & 7;
                cpa16(base + row * GPITCH + seg * 16,
                      A + (long long)(bm0 + row) * lda + kc + seg * 8);
            } else {               // B: 128 rows x 8 segs
                const int idx = tid + (it - 8) * 256;
                const int row = idx >> 3, seg = idx & 7;
                cpa16(base + GSUBTA + row * GPITCH + seg * 16,
                      Bm + (long long)(bn0 + row) * ldb + kc + seg * 8);
            }
        }
    };

    float acc[4][8][4];
    #pragma unroll
    for (int i = 0; i < 4; i++)
        #pragma unroll
        for (int j = 0; j < 8; j++)
            #pragma unroll
            for (int e = 0; e < 4; e++) acc[i][j][e] = 0.0f;

    stage(0); cpa_commit();
    stage(1); cpa_commit();

    const int arow = wm * 64 + (lane & 15);              // + mt*16 (mt 0..3)
    const int asel = (lane >> 4);
    const int brow = wn * 64 + (lane & 7) + ((lane >> 4) << 3);  // + pr*16
    const int bsel = (lane >> 3) & 1;

    for (int i = 0; i < nk; i++) {
        if (i + 1 < nk) cpa_wait1(); else cpa_wait0();
        __syncthreads();
        const unsigned base = sb + (i & 1) * GSTAGE;

        #pragma unroll
        for (int ks = 0; ks < 4; ks++) {
            unsigned ah[4][4];
            #pragma unroll
            for (int mt = 0; mt < 4; mt++)
                ldsm4(ah[mt], base + (arow + mt * 16) * GPITCH + (ks * 2 + asel) * 16);
            #pragma unroll
            for (int pr = 0; pr < 4; pr++) {
                unsigned bh[4];
                ldsm4(bh, base + GSUBTA + (brow + pr * 16) * GPITCH + (ks * 2 + bsel) * 16);
                #pragma unroll
                for (int mt = 0; mt < 4; mt++)
                    #pragma unroll
                    for (int hf = 0; hf < 2; hf++)
                        mma16816(acc[mt][pr * 2 + hf], ah[mt], &bh[hf * 2]);
            }
        }
        __syncthreads();
        if (i + 2 < nk) { stage(i + 2); cpa_commit(); }
    }

    // Epilogue
    const int er = bm0 + wm * 64 + (lane >> 2);
    const int ec = bn0 + wn * 64 + (lane & 3) * 2;
    #pragma unroll
    for (int mt = 0; mt < 4; mt++)
        #pragma unroll
        for (int nt = 0; nt < 8; nt++) {
            const float* c = acc[mt][nt];
            const int row = er + mt * 16;
            const int col = ec + nt * 8;
            if (EPI == 0) {
                const long long gi0 = (long long)row * ldc + col;
                const long long gi1 = (long long)(row + 8) * ldc + col;
                *(float2*)(Cf + gi0) = make_float2(c[0], c[1]);
                *(float2*)(Cf + gi1) = make_float2(c[2], c[3]);
            } else {
                const int s0r = row & (S_ - 1);
                const int s1r = (row + 8) & (S_ - 1);
                if (col < DIM_) {                      // ---- Q: RoPE -> qhi
                    const int ip = (col & 127) >> 1;
                    const float c0 = cs[s0r * 64 + ip], sv0 = sn[s0r * 64 + ip];
                    const float c1 = cs[s1r * 64 + ip], sv1 = sn[s1r * 64 + ip];
                    *(__half2*)(qp + (long long)row * DIM_ + col) =
                        __floats2half2_rn(c[0] * c0 - c[1] * sv0, c[0] * sv0 + c[1] * c0);
                    *(__half2*)(qp + (long long)(row + 8) * DIM_ + col) =
                        __floats2half2_rn(c[2] * c1 - c[3] * sv1, c[2] * sv1 + c[3] * c1);
                } else if (col < DIM_ + KVW_) {        // ---- K: RoPE -> khi
                    const int c2 = col - DIM_;
                    const int ip = (c2 & 127) >> 1;
                    const float c0 = cs[s0r * 64 + ip], sv0 = sn[s0r * 64 + ip];
                    const float c1 = cs[s1r * 64 + ip], sv1 = sn[s1r * 64 + ip];
                    *(__half2*)(kp + (long long)row * KVW_ + c2) =
                        __floats2half2_rn(c[0] * c0 - c[1] * sv0, c[0] * sv0 + c[1] * c0);
                    *(__half2*)(kp + (long long)(row + 8) * KVW_ + c2) =
                        __floats2half2_rn(c[2] * c1 - c[3] * sv1, c[2] * sv1 + c[3] * c1);
                } else {                               // ---- V: fp16 transposed -> vthi
                    const int c3 = col - (DIM_ + KVW_);
                    const int kv = c3 >> 7, d = c3 & 127;
                    const int b  = row >> 11;
                    const size_t base = ((size_t)(b * NKV_ + kv) * HD_ + d) * S_ + s0r;
                    vp[base]           = __float2half(c[0]);
                    vp[base + S_]      = __float2half(c[1]);
                    vp[base + 8]       = __float2half(c[2]);
                    vp[base + S_ + 8]  = __float2half(c[3]);
                }
            }
        }
}

// ===========================================================================
// Fused flash attention (unchanged — validated).
// ===========================================================================
constexpr int FP    = 272;
constexpr int FTILE = 128 * FP;
constexpr int FSMEM = 4 * FTILE;       // 139264 B

__global__ __launch_bounds__(256, 1)
void flash_k(const __half* __restrict__ qhi, const __half* __restrict__ khi,
             const __half* __restrict__ vthi, __half* __restrict__ outp,
             float scale)
{
    const int bi = blockIdx.x;
    const int bh = blockIdx.y;
    const int b  = bh >> 5, h = bh & 31;
    const int kv = h >> 2;
    const int bm0 = bi * 128;

    extern __shared__ char smem[];
    const unsigned sb = smem_u32(smem);
    const int tid = threadIdx.x, lane = tid & 31, w = tid >> 5;

    #pragma unroll
    for (int it = 0; it < 8; it++) {
        const int idx = tid + it * 256;
        const int row = idx >> 4, seg = idx & 15;
        cpa16(sb + row * FP + seg * 16,
              qhi + ((size_t)((b * S_ + bm0 + row) * NH_ + h)) * HD_ + seg * 8);
    }
    cpa_commit(); cpa_wait0(); __syncthreads();

    unsigned qa[8][4];
    {
        const int ar = w * 16 + (lane & 15);
        const int as = lane >> 4;
        #pragma unroll
        for (int t = 0; t < 8; t++)
            ldsm4(qa[t], sb + ar * FP + (t * 2 + as) * 16);
    }
    __syncthreads();

    const int nk = bi + 1;
    auto stageKV = [&](int j) {
        const unsigned kb = sb + (j & 1) * (2 * FTILE);
        const unsigned vb = kb + FTILE;
        #pragma unroll
        for (int it = 0; it < 8; it++) {
            const int idx = tid + it * 256;
            const int row = idx >> 4, seg = idx & 15;
            cpa16(kb + row * FP + seg * 16,
                  khi + ((size_t)((b * S_ + j * 128 + row) * NKV_ + kv)) * HD_ + seg * 8);
            cpa16(vb + row * FP + seg * 16,
                  vthi + ((size_t)((b * NKV_ + kv) * HD_ + row)) * S_ + j * 128 + seg * 8);
        }
    };

    stageKV(0); cpa_commit();
    if (nk > 1) { stageKV(1); cpa_commit(); }

    float oacc[16][4];
    #pragma unroll
    for (int i = 0; i < 16; i++)
        #pragma unroll
        for (int e = 0; e < 4; e++) oacc[i][e] = 0.0f;
    float m0 = -1e30f, m1 = -1e30f, l0 = 0.0f, l1 = 0.0f;

    const int bro = (lane & 7) + ((lane >> 4) << 3);
    const int bsl = (lane >> 3) & 1;

    for (int j = 0; j < nk; j++) {
        if (j + 1 < nk) cpa_wait1(); else cpa_wait0();
        __syncthreads();
        const unsigned kb = sb + (j & 1) * (2 * FTILE);
        const unsigned vb = kb + FTILE;

        float sacc[16][4];
        #pragma unroll
        for (int i = 0; i < 16; i++)
            #pragma unroll
            for (int e = 0; e < 4; e++) sacc[i][e] = 0.0f;
        #pragma unroll
        for (int t = 0; t < 8; t++)
            #pragma unroll
            for (int pn = 0; pn < 8; pn++) {
                unsigned bb[4];
                ldsm4(bb, kb + (pn * 16 + bro) * FP + (t * 2 + bsl) * 16);
                mma16816(sacc[2 * pn],     qa[t], bb);
                mma16816(sacc[2 * pn + 1], qa[t], bb + 2);
            }

        if (j == bi) {
            const int r0 = w * 16 + (lane >> 2);
            const int cb = (lane & 3) * 2;
            #pragma unroll
            for (int nt = 0; nt < 16; nt++) {
                const int c0 = nt * 8 + cb;
                if (c0     > r0)     sacc[nt][0] = -1e30f;
                if (c0 + 1 > r0)     sacc[nt][1] = -1e30f;
                if (c0     > r0 + 8) sacc[nt][2] = -1e30f;
                if (c0 + 1 > r0 + 8) sacc[nt][3] = -1e30f;
            }
        }

        float mx0 = -1e30f, mx1 = -1e30f;
        #pragma unroll
        for (int nt = 0; nt < 16; nt++) {
            mx0 = fmaxf(mx0, fmaxf(sacc[nt][0], sacc[nt][1]));
            mx1 = fmaxf(mx1, fmaxf(sacc[nt][2], sacc[nt][3]));
        }
        mx0 = fmaxf(mx0, __shfl_xor_sync(0xffffffffu, mx0, 1));
        mx0 = fmaxf(mx0, __shfl_xor_sync(0xffffffffu, mx0, 2));
        mx1 = fmaxf(mx1, __shfl_xor_sync(0xffffffffu, mx1, 1));
        mx1 = fmaxf(mx1, __shfl_xor_sync(0xffffffffu, mx1, 2));
        const float mn0 = fmaxf(m0, mx0 * scale);
        const float mn1 = fmaxf(m1, mx1 * scale);
        const float a0 = expf(m0 - mn0);
        const float a1 = expf(m1 - mn1);
        m0 = mn0; m1 = mn1;
        #pragma unroll
        for (int nt = 0; nt < 16; nt++) {
            oacc[nt][0] *= a0; oacc[nt][1] *= a0;
            oacc[nt][2] *= a1; oacc[nt][3] *= a1;
        }

        float rs0 = 0.0f, rs1 = 0.0f;
        unsigned pa[8][4];
        #pragma unroll
        for (int t = 0; t < 8; t++) {
            const float e0 = expf(sacc[2 * t][0] * scale - mn0);
            const float e1 = expf(sacc[2 * t][1] * scale - mn0);
            const float e2 = expf(sacc[2 * t][2] * scale - mn1);
            const float e3 = expf(sacc[2 * t][3] * scale - mn1);
            const float f0 = expf(sacc[2 * t + 1][0] * scale - mn0);
            const float f1 = expf(sacc[2 * t + 1][1] * scale - mn0);
            const float f2 = expf(sacc[2 * t + 1][2] * scale - mn1);
            const float f3 = expf(sacc[2 * t + 1][3] * scale - mn1);
            rs0 += e0 + e1 + f0 + f1;
            rs1 += e2 + e3 + f2 + f3;
            __half2 p0 = __floats2half2_rn(e0, e1);
            __half2 p1 = __floats2half2_rn(e2, e3);
            __half2 p2 = __floats2half2_rn(f0, f1);
            __half2 p3 = __floats2half2_rn(f2, f3);
            pa[t][0] = *(unsigned*)&p0;
            pa[t][1] = *(unsigned*)&p1;
            pa[t][2] = *(unsigned*)&p2;
            pa[t][3] = *(unsigned*)&p3;
        }
        rs0 += __shfl_xor_sync(0xffffffffu, rs0, 1);
        rs0 += __shfl_xor_sync(0xffffffffu, rs0, 2);
        rs1 += __shfl_xor_sync(0xffffffffu, rs1, 1);
        rs1 += __shfl_xor_sync(0xffffffffu, rs1, 2);
        l0 = l0 * a0 + rs0;
        l1 = l1 * a1 + rs1;

        #pragma unroll
        for (int t = 0; t < 8; t++)
            #pragma unroll
            for (int pn = 0; pn < 8; pn++) {
                unsigned bb[4];
                ldsm4(bb, vb + (pn * 16 + bro) * FP + (t * 2 + bsl) * 16);
                mma16816(oacc[2 * pn],     pa[t], bb);
                mma16816(oacc[2 * pn + 1], pa[t], bb + 2);
            }

        __syncthreads();
        if (j + 2 < nk) { stageKV(j + 2); cpa_commit(); }
    }

    const float i0 = 1.0f / l0, i1 = 1.0f / l1;
    const int r0 = bm0 + w * 16 + (lane >> 2);
    const int cb = (lane & 3) * 2;
    #pragma unroll
    for (int nt = 0; nt < 16; nt++) {
        const int col = nt * 8 + cb;
        const size_t g0 = ((size_t)((b * S_ + r0) * NH_ + h)) * HD_ + col;
        const size_t g1 = ((size_t)((b * S_ + r0 + 8) * NH_ + h)) * HD_ + col;
        *(__half2*)(outp + g0) = __floats2half2_rn(oacc[nt][0] * i0, oacc[nt][1] * i0);
        *(__half2*)(outp + g1) = __floats2half2_rn(oacc[nt][2] * i1, oacc[nt][3] * i1);
    }
}

// ---------------------------------------------------------------------------
// Elementwise fp32 -> fp16
// ---------------------------------------------------------------------------
__global__ __launch_bounds__(256)
void split_k(const float4* __restrict__ s, __half2* __restrict__ h2, int n4)
{
    int i = blockIdx.x * 256 + threadIdx.x;
    if (i >= n4) return;
    float4 v = s[i];
    h2[2 * i]     = __floats2half2_rn(v.x, v.y);
    h2[2 * i + 1] = __floats2half2_rn(v.z, v.w);
}

// ---------------------------------------------------------------------------
// Inputs (metadata order): x, wq, wk, wv, wo, freqs_cos, freqs_sin
// ---------------------------------------------------------------------------
extern "C" void kernel_launch(void* const* d_in, const int* in_sizes, int n_in,
                              void* d_out, int out_size)
{
    const float* x  = (const float*)d_in[0];
    const float* wq = (const float*)d_in[1];
    const float* wk = (const float*)d_in[2];
    const float* wv = (const float*)d_in[3];
    const float* wo = (const float*)d_in[4];
    const float* fc = (const float*)d_in[5];
    const float* fs = (const float*)d_in[6];
    float* out = (float*)d_out;

    __half *xhi, *wqkv, *wohi, *qhi, *khi, *vthi, *ahi;
    cudaGetSymbolAddress((void**)&xhi,  g_xhi);
    cudaGetSymbolAddress((void**)&wqkv, g_wqkv);
    cudaGetSymbolAddress((void**)&wohi, g_wohi);
    cudaGetSymbolAddress((void**)&qhi,  g_qhi);
    cudaGetSymbolAddress((void**)&khi,  g_khi);
    cudaGetSymbolAddress((void**)&vthi, g_vthi);
    cudaGetSymbolAddress((void**)&ahi,  g_ahi);

    cudaFuncSetAttribute(gemm64<0>, cudaFuncAttributeMaxDynamicSharedMemorySize, GSMEM);
    cudaFuncSetAttribute(gemm64<3>, cudaFuncAttributeMaxDynamicSharedMemorySize, GSMEM);
    cudaFuncSetAttribute(flash_k, cudaFuncAttributeMaxDynamicSharedMemorySize, FSMEM);

    const float scale = 0.08838834764831845f;  // 1/sqrt(128)

    // 1) convert inputs to fp16 (wq|wk|wv concatenated: 4096 + 1024 + 1024 rows)
    split_k<<<16384, 256>>>((const float4*)x,  (__half2*)xhi,               4194304);
    split_k<<<16384, 256>>>((const float4*)wq, (__half2*)wqkv,              4194304);
    split_k<<<4096,  256>>>((const float4*)wk, (__half2*)(wqkv + 16777216), 1048576);
    split_k<<<4096,  256>>>((const float4*)wv, (__half2*)(wqkv + 20971520), 1048576);
    split_k<<<16384, 256>>>((const float4*)wo, (__half2*)wohi,              4194304);

    // 2) fused QKV projection (M=4096, N=6144): Q->rope, K->rope, V->vthi^T
    gemm64<3><<<dim3(NQKV / 128, DIM_ / 256), 256, GSMEM>>>(
        xhi, wqkv, nullptr, qhi, khi, vthi, fc, fs, DIM_, DIM_, DIM_, 0);

    // 3) fused flash attention (QK^T + causal online softmax + P V)
    flash_k<<<dim3(S_ / 128, B_ * NH_), 256, FSMEM>>>(qhi, khi, vthi, ahi, scale);

    // 4) output projection (fp32 out)
    gemm64<0><<<dim3(DIM_ / 128, DIM_ / 256), 256, GSMEM>>>(
        ahi, wohi, out, nullptr, nullptr, nullptr, nullptr, nullptr,
        DIM_, DIM_, DIM_, DIM_);
}